// round 16
// baseline (speedup 1.0000x reference)
#include <cuda_runtime.h>
#include <cuda_bf16.h>
#include <cstdint>

// Shapes (fixed by the problem)
#define SEQ   192
#define BATCH 2
#define C_P   128
#define C     32
#define C_I   128

// ---------------------------------------------------------------------------
// Global scratch
// A fragments: [b][plane][ks(2)][itile(12)][lane(32)][reg(4)] as bf16x2 words
__device__ uint32_t g_p1f[BATCH * 2 * 2 * 12 * 32 * 4];      // 49 KB
// p2 transposed fp32: [b][d][s]
__device__ float    g_p2t[BATCH * C * SEQ];

// ---- packed fp32x2 helpers ---------------------------------------------------
#define FMA_F32X2(d, a, b, c) \
    asm("fma.rn.f32x2 %0, %1, %2, %3;" : "=l"(d) : "l"(a), "l"(b), "l"(c))
#define PACK_F32X2(out, lo, hi) \
    asm("mov.b64 %0, {%1, %2};" : "=l"(out) : "r"(__float_as_uint(lo)), "r"(__float_as_uint(hi)))
#define UNPACK_F32X2(lo, hi, in) \
    do { unsigned int _l, _h; \
         asm("mov.b64 {%0, %1}, %2;" : "=r"(_l), "=r"(_h) : "l"(in)); \
         lo = __uint_as_float(_l); hi = __uint_as_float(_h); } while (0)

// bf16 mma: D += A * B,  m16n8k16, fp32 accumulate
#define MMA_BF16(d, a, b) \
    asm volatile("mma.sync.aligned.m16n8k16.row.col.f32.bf16.bf16.f32 " \
        "{%0,%1,%2,%3}, {%4,%5,%6,%7}, {%8,%9}, {%0,%1,%2,%3};" \
        : "+f"((d)[0]), "+f"((d)[1]), "+f"((d)[2]), "+f"((d)[3]) \
        : "r"((a).x), "r"((a).y), "r"((a).z), "r"((a).w), \
          "r"((b).x), "r"((b).y))

__device__ __forceinline__ void bf16_split(float v, uint32_t& h, uint32_t& l) {
    __nv_bfloat16 hb = __float2bfloat16(v);
    float hf = __bfloat162float(hb);
    __nv_bfloat16 lb = __float2bfloat16(v - hf);
    h = (uint32_t)__bfloat16_as_ushort(hb);
    l = (uint32_t)__bfloat16_as_ushort(lb);
}

__device__ __forceinline__ uint32_t smem_u32(const void* p) {
    uint32_t a;
    asm("{ .reg .u64 t; cvta.to.shared.u64 t, %1; cvt.u32.u64 %0, t; }"
        : "=r"(a) : "l"(p));
    return a;
}

// ---------------------------------------------------------------------------
// Kernel 1: LayerNorm + dual projections. (R13 version — W preloaded to regs)
// ---------------------------------------------------------------------------
__global__ __launch_bounds__(256)
void k1_ln_proj(const float* __restrict__ p,
                const float* __restrict__ gamma,
                const float* __restrict__ beta,
                const float* __restrict__ W1,
                const float* __restrict__ b1,
                const float* __restrict__ W2,
                const float* __restrict__ b2) {
    const int r = blockIdx.x;
    const int s = r / BATCH;
    const int b = r % BATCH;
    const int tid = threadIdx.x;

    __shared__ float a1[4], a2[4];
    __shared__ float sh_pn[C_P];
    __shared__ float sh_res[64];

    const int  o = tid >> 2;
    const int  t = tid & 3;
    const int  c = (o < 32) ? o : (o - 32);
    const float* W = (o < 32) ? W1 : W2;
    float4 wreg[8];
    #pragma unroll
    for (int u = 0; u < 8; ++u)
        wreg[u] = ((const float4*)(W + c * C_P))[t + 4 * u];

    float x = 0.f, gm = 0.f, bt = 0.f;
    if (tid < C_P) {
        x  = p[r * C_P + tid];
        gm = gamma[tid];
        bt = beta[tid];
    }

    if (tid < C_P) {
        float s1 = x, s2 = x * x;
        #pragma unroll
        for (int off = 16; off > 0; off >>= 1) {
            s1 += __shfl_down_sync(0xFFFFFFFFu, s1, off);
            s2 += __shfl_down_sync(0xFFFFFFFFu, s2, off);
        }
        const int warp = tid >> 5, lane = tid & 31;
        if (lane == 0) { a1[warp] = s1; a2[warp] = s2; }
    }
    __syncthreads();

    if (tid < C_P) {
        float sum  = a1[0] + a1[1] + a1[2] + a1[3];
        float sumq = a2[0] + a2[1] + a2[2] + a2[3];
        const float inv = 1.0f / (float)C_P;
        float mu   = sum * inv;
        float var  = sumq * inv - mu * mu;
        float rstd = rsqrtf(var + 1e-5f);
        sh_pn[tid] = (x - mu) * rstd * gm + bt;
    }
    __syncthreads();

    const float4* pn4 = (const float4*)sh_pn;
    float acc0 = 0.f, acc1 = 0.f;
    #pragma unroll
    for (int u = 0; u < 8; u += 2) {
        float4 v0 = pn4[t + 4 * u];
        float4 v1 = pn4[t + 4 * (u + 1)];
        acc0 += wreg[u].x*v0.x + wreg[u].y*v0.y + wreg[u].z*v0.z + wreg[u].w*v0.w;
        acc1 += wreg[u+1].x*v1.x + wreg[u+1].y*v1.y + wreg[u+1].z*v1.z + wreg[u+1].w*v1.w;
    }
    float val = acc0 + acc1;
    val += __shfl_xor_sync(0xFFFFFFFFu, val, 1);
    val += __shfl_xor_sync(0xFFFFFFFFu, val, 2);
    if (t == 0) sh_res[o] = val;
    __syncthreads();

    if (tid < 64) {
        if (tid < 32) {
            float v1 = sh_res[tid] + b1[tid];
            uint32_t hu, lu;
            bf16_split(v1, hu, lu);
            uint32_t hu1 = __shfl_down_sync(0xFFFFFFFFu, hu, 1);
            uint32_t lu1 = __shfl_down_sync(0xFFFFFFFFu, lu, 1);
            if ((tid & 1) == 0) {
                const int cch  = tid;
                const int it   = s >> 4;
                const int grow = s & 15;
                const int g    = grow & 7;
                const int top  = grow >> 3;
                const int ks   = cch >> 4;
                const int cl   = cch & 15;
                const int rhi  = cl >> 3;
                const int tt   = (cl & 7) >> 1;
                const int reg  = top + 2 * rhi;
                const int ln   = g * 4 + tt;
                const int i0 = ((((b * 2 + 0) * 2 + ks) * 12 + it) * 32 + ln) * 4 + reg;
                const int i1 = ((((b * 2 + 1) * 2 + ks) * 12 + it) * 32 + ln) * 4 + reg;
                g_p1f[i0] = hu | (hu1 << 16);
                g_p1f[i1] = lu | (lu1 << 16);
            }
        } else {
            float v2 = sh_res[tid] + b2[tid - 32];
            g_p2t[(b * C + (tid - 32)) * SEQ + s] = v2;
        }
    }
}

// ---------------------------------------------------------------------------
// Kernel 3 (fused M-build + MMA + TMA-store epilogue), occupancy 3.
// grid = 768 (bk x 3 j-thirds of 64 cols), 256 threads.
// A fragments prefetched via cp.async into smem (overlaps M-build); the
// output tile image ALIASES the A buffer (A dies at MMA end, tile born after).
// ---------------------------------------------------------------------------
#define TILE_PITCH 72                    // floats per tile row
#define SB_WORDS   (2 * 2 * 8 * 32 * 2)  // 2048 u32 = 8 KB
#define SA_U4      (2 * 2 * 12 * 32)     // 1536 uint4 = 24 KB (per batch b)
#define TILE_FLOATS (SEQ * TILE_PITCH)   // 13824 floats = 54 KB
#define K3_SMEM_BYTES (SB_WORDS * 4 + TILE_FLOATS * 4)   // 8 KB + 54 KB = 62 KB

__global__ __launch_bounds__(256, 3)
void k3_fused(const float* __restrict__ Wout,
              const float* __restrict__ bout,
              float* __restrict__ out) {
    extern __shared__ uint32_t dynsm[];
    uint32_t* sB   = dynsm;                          // 8 KB
    uint4*    sA   = (uint4*)(dynsm + SB_WORDS);     // 24 KB (aliases tile)
    float*    tile = (float*)(dynsm + SB_WORDS);     // 54 KB (after MMA)
    __shared__ float shW[C * C];                     // 4 KB static

    const int blk    = blockIdx.x;
    const int bk     = blk / 3;
    const int jthird = blk - 3 * bk;
    const int b      = bk >> 7;
    const int k      = bk & (C_I - 1);
    const int tid    = threadIdx.x;
    const int wid    = tid >> 5, lane = tid & 31;
    const int wi     = wid >> 1;                 // 0..3 i-band (48 rows)
    const int wj     = wid & 1;                  // 0..1 j-band (32 cols)

    // ---- cp.async prefetch of A fragments (streams during M-build) ----
    {
        const uint4* Ag = (const uint4*)g_p1f + (size_t)b * SA_U4;
        const uint32_t sa_base = smem_u32(sA);
        #pragma unroll
        for (int i = 0; i < 6; ++i) {
            const int idx = tid + i * 256;
            asm volatile("cp.async.cg.shared.global [%0], [%1], 16;"
                         :: "r"(sa_base + idx * 16), "l"(Ag + idx) : "memory");
        }
        asm volatile("cp.async.commit_group;" ::: "memory");
    }

    ((float4*)shW)[tid] = ((const float4*)(Wout + (size_t)k * C * C))[tid];

    // ---- M-build operand loads ----
    const int jloc = tid & 63;
    const int rest = tid >> 6;
    const int ks   = rest & 1;
    const int ch   = rest >> 1;
    const int j    = jthird * 64 + jloc;
    const float* P2 = g_p2t + (size_t)b * C * SEQ;

    unsigned long long qq[16];
    #pragma unroll
    for (int d2 = 0; d2 < 16; ++d2) {
        float qa = P2[(2 * d2 + 0) * SEQ + j];
        float qb = P2[(2 * d2 + 1) * SEQ + j];
        PACK_F32X2(qq[d2], qa, qb);
    }
    __syncthreads();   // shW visible

    // ---- M build: thread = (jloc, ks, ch), 8 c's each ----
    {
        const int jt = jloc >> 3;
        const int g  = jloc & 7;
        float m[8];
        #pragma unroll
        for (int cc = 0; cc < 8; ++cc) {
            const int c = ks * 16 + ch * 8 + cc;
            const uint4* w4 = (const uint4*)(shW + c * C);
            unsigned long long acca = 0ull, accb = 0ull;
            #pragma unroll
            for (int d4 = 0; d4 < 4; ++d4) {
                uint4 wlo = w4[d4];
                uint4 whi = w4[d4 + 4];
                unsigned long long w0, w1, w2v, w3;
                asm("mov.b64 %0, {%1, %2};" : "=l"(w0) : "r"(wlo.x), "r"(wlo.y));
                asm("mov.b64 %0, {%1, %2};" : "=l"(w1) : "r"(wlo.z), "r"(wlo.w));
                asm("mov.b64 %0, {%1, %2};" : "=l"(w2v) : "r"(whi.x), "r"(whi.y));
                asm("mov.b64 %0, {%1, %2};" : "=l"(w3) : "r"(whi.z), "r"(whi.w));
                FMA_F32X2(acca, qq[2 * d4 + 0],     w0,  acca);
                FMA_F32X2(acca, qq[2 * d4 + 1],     w1,  acca);
                FMA_F32X2(accb, qq[8 + 2 * d4 + 0], w2v, accb);
                FMA_F32X2(accb, qq[8 + 2 * d4 + 1], w3,  accb);
            }
            float la, ha, lb2, hb2;
            UNPACK_F32X2(la, ha, acca);
            UNPACK_F32X2(lb2, hb2, accb);
            m[cc] = (la + ha) + (lb2 + hb2);
        }
        #pragma unroll
        for (int t = 0; t < 4; ++t) {
            uint32_t h0, l0, h1, l1;
            bf16_split(m[2 * t],     h0, l0);
            bf16_split(m[2 * t + 1], h1, l1);
            const int ln = g * 4 + t;
            sB[((0 * 2 + ks) * 8 + jt) * 64 + ln * 2 + ch] = h0 | (h1 << 16);
            sB[((1 * 2 + ks) * 8 + jt) * 64 + ln * 2 + ch] = l0 | (l1 << 16);
        }
    }
    asm volatile("cp.async.wait_group 0;" ::: "memory");
    __syncthreads();   // sB + sA visible to all

    // ---- MMA (A and B both from smem) ----
    float acc[3][4][4];
    #pragma unroll
    for (int i = 0; i < 3; ++i)
        #pragma unroll
        for (int jx = 0; jx < 4; ++jx)
            #pragma unroll
            for (int q = 0; q < 4; ++q) acc[i][jx][q] = 0.0f;

    #pragma unroll
    for (int kss = 0; kss < 2; ++kss) {
        uint2 Bh[4];
        #pragma unroll
        for (int jtl = 0; jtl < 4; ++jtl) {
            const int jt = wj * 4 + jtl;
            Bh[jtl] = *(const uint2*)&sB[((0 * 2 + kss) * 8 + jt) * 64 + lane * 2];
        }
        uint4 Ah[3];
        #pragma unroll
        for (int itl = 0; itl < 3; ++itl)
            Ah[itl] = sA[((0 * 2 + kss) * 12 + (wi * 3 + itl)) * 32 + lane];
        #pragma unroll
        for (int itl = 0; itl < 3; ++itl)
            #pragma unroll
            for (int jtl = 0; jtl < 4; ++jtl)
                MMA_BF16(acc[itl][jtl], Ah[itl], Bh[jtl]);

        {
            uint4 Al[3];
            #pragma unroll
            for (int itl = 0; itl < 3; ++itl)
                Al[itl] = sA[((1 * 2 + kss) * 12 + (wi * 3 + itl)) * 32 + lane];
            #pragma unroll
            for (int itl = 0; itl < 3; ++itl)
                #pragma unroll
                for (int jtl = 0; jtl < 4; ++jtl)
                    MMA_BF16(acc[itl][jtl], Al[itl], Bh[jtl]);
        }
        {
            uint2 Bl[4];
            #pragma unroll
            for (int jtl = 0; jtl < 4; ++jtl) {
                const int jt = wj * 4 + jtl;
                Bl[jtl] = *(const uint2*)&sB[((1 * 2 + kss) * 8 + jt) * 64 + lane * 2];
            }
            #pragma unroll
            for (int itl = 0; itl < 3; ++itl)
                #pragma unroll
                for (int jtl = 0; jtl < 4; ++jtl)
                    MMA_BF16(acc[itl][jtl], Ah[itl], Bl[jtl]);
        }
    }
    __syncthreads();   // all sA reads done: tile may now overwrite it

    // ---- epilogue: STS.64 into tile image, then per-row TMA bulk store ----
    const float bias = bout[k];
    const int g = lane >> 2, t = lane & 3;
    #pragma unroll
    for (int itl = 0; itl < 3; ++itl) {
        const int row0 = wi * 48 + itl * 16 + g;
        #pragma unroll
        for (int jtl = 0; jtl < 4; ++jtl) {
            const int col = wj * 32 + jtl * 8 + 2 * t;
            float2 v0, v1;
            v0.x = (acc[itl][jtl][0] + bias) * 0.5f;
            v0.y = (acc[itl][jtl][1] + bias) * 0.5f;
            v1.x = (acc[itl][jtl][2] + bias) * 0.5f;
            v1.y = (acc[itl][jtl][3] + bias) * 0.5f;
            *(float2*)&tile[row0 * TILE_PITCH + col]       = v0;
            *(float2*)&tile[(row0 + 8) * TILE_PITCH + col] = v1;
        }
    }
    __syncthreads();

    if (tid < SEQ) {
        asm volatile("fence.proxy.async.shared::cta;" ::: "memory");
        const uint32_t src = smem_u32(tile) + (uint32_t)(tid * TILE_PITCH * 4);
        float* dst = out + ((size_t)bk * SEQ + tid) * SEQ + jthird * 64;
        asm volatile(
            "cp.async.bulk.global.shared::cta.bulk_group [%0], [%1], %2;"
            :: "l"(dst), "r"(src), "r"(256) : "memory");
        asm volatile("cp.async.bulk.commit_group;" ::: "memory");
        asm volatile("cp.async.bulk.wait_group 0;" ::: "memory");
    }
}

// ---------------------------------------------------------------------------
extern "C" void kernel_launch(void* const* d_in, const int* in_sizes, int n_in,
                              void* d_out, int out_size) {
    const float* p     = (const float*)d_in[0];
    const float* gamma = (const float*)d_in[1];
    const float* beta  = (const float*)d_in[2];
    const float* W1    = (const float*)d_in[3];
    const float* b1    = (const float*)d_in[4];
    const float* W2    = (const float*)d_in[5];
    const float* b2    = (const float*)d_in[6];
    const float* Wout  = (const float*)d_in[7];
    const float* bout  = (const float*)d_in[8];
    float* out = (float*)d_out;

    cudaFuncSetAttribute(k3_fused, cudaFuncAttributeMaxDynamicSharedMemorySize,
                         K3_SMEM_BYTES);

    k1_ln_proj<<<SEQ * BATCH, 256>>>(p, gamma, beta, W1, b1, W2, b2);
    k3_fused<<<BATCH * C_I * 3, 256, K3_SMEM_BYTES>>>(Wout, bout, out);
}

// round 17
// speedup vs baseline: 1.0875x; 1.0875x over previous
#include <cuda_runtime.h>
#include <cuda_bf16.h>
#include <cstdint>

// Shapes (fixed by the problem)
#define SEQ   192
#define BATCH 2
#define C_P   128
#define C     32
#define C_I   128

// ---------------------------------------------------------------------------
// Global scratch
// A fragments: [b][plane][ks(2)][itile(12)][lane(32)][reg(4)] as bf16x2 words
__device__ uint32_t g_p1f[BATCH * 2 * 2 * 12 * 32 * 4];      // 49 KB
// p2 transposed fp32: [b][d][s]
__device__ float    g_p2t[BATCH * C * SEQ];

// ---- packed fp32x2 helpers ---------------------------------------------------
#define FMA_F32X2(d, a, b, c) \
    asm("fma.rn.f32x2 %0, %1, %2, %3;" : "=l"(d) : "l"(a), "l"(b), "l"(c))
#define PACK_F32X2(out, lo, hi) \
    asm("mov.b64 %0, {%1, %2};" : "=l"(out) : "r"(__float_as_uint(lo)), "r"(__float_as_uint(hi)))
#define UNPACK_F32X2(lo, hi, in) \
    do { unsigned int _l, _h; \
         asm("mov.b64 {%0, %1}, %2;" : "=r"(_l), "=r"(_h) : "l"(in)); \
         lo = __uint_as_float(_l); hi = __uint_as_float(_h); } while (0)

// bf16 mma: D += A * B,  m16n8k16, fp32 accumulate
#define MMA_BF16(d, a, b) \
    asm volatile("mma.sync.aligned.m16n8k16.row.col.f32.bf16.bf16.f32 " \
        "{%0,%1,%2,%3}, {%4,%5,%6,%7}, {%8,%9}, {%0,%1,%2,%3};" \
        : "+f"((d)[0]), "+f"((d)[1]), "+f"((d)[2]), "+f"((d)[3]) \
        : "r"((a).x), "r"((a).y), "r"((a).z), "r"((a).w), \
          "r"((b).x), "r"((b).y))

__device__ __forceinline__ void bf16_split(float v, uint32_t& h, uint32_t& l) {
    __nv_bfloat16 hb = __float2bfloat16(v);
    float hf = __bfloat162float(hb);
    __nv_bfloat16 lb = __float2bfloat16(v - hf);
    h = (uint32_t)__bfloat16_as_ushort(hb);
    l = (uint32_t)__bfloat16_as_ushort(lb);
}

// ---------------------------------------------------------------------------
// Kernel 1: LayerNorm + dual projections (R7/R11 version — measured best rest).
// 256 threads: o = tid>>2 (0..63 outputs), t = tid&3 (channel quarter).
// ---------------------------------------------------------------------------
__global__ __launch_bounds__(256)
void k1_ln_proj(const float* __restrict__ p,
                const float* __restrict__ gamma,
                const float* __restrict__ beta,
                const float* __restrict__ W1,
                const float* __restrict__ b1,
                const float* __restrict__ W2,
                const float* __restrict__ b2) {
    const int r = blockIdx.x;
    const int s = r / BATCH;
    const int b = r % BATCH;
    const int tid = threadIdx.x;

    __shared__ float a1[4], a2[4];
    __shared__ float sh_pn[C_P];
    __shared__ float sh_res[64];

    if (tid < C_P) {
        float x = p[r * C_P + tid];
        float s1 = x, s2 = x * x;
        #pragma unroll
        for (int off = 16; off > 0; off >>= 1) {
            s1 += __shfl_down_sync(0xFFFFFFFFu, s1, off);
            s2 += __shfl_down_sync(0xFFFFFFFFu, s2, off);
        }
        const int warp = tid >> 5, lane = tid & 31;
        if (lane == 0) { a1[warp] = s1; a2[warp] = s2; }
        sh_pn[tid] = x;
    }
    __syncthreads();
    {
        float sum  = a1[0] + a1[1] + a1[2] + a1[3];
        float sumq = a2[0] + a2[1] + a2[2] + a2[3];
        const float inv = 1.0f / (float)C_P;
        float mu   = sum * inv;
        float var  = sumq * inv - mu * mu;
        float rstd = rsqrtf(var + 1e-5f);
        __syncthreads();
        if (tid < C_P) {
            float x = sh_pn[tid];
            sh_pn[tid] = (x - mu) * rstd * gamma[tid] + beta[tid];
        }
    }
    __syncthreads();

    const int  o = tid >> 2;
    const int  t = tid & 3;
    const int  c = (o < 32) ? o : (o - 32);
    const float* W = (o < 32) ? W1 : W2;

    const float4* w4  = (const float4*)(W + c * C_P);
    const float4* pn4 = (const float4*)sh_pn;
    float acc0 = 0.f, acc1 = 0.f;
    #pragma unroll
    for (int u = 0; u < 8; u += 2) {
        float4 w, v;
        int f0 = t + 4 * u, f1 = t + 4 * (u + 1);
        w = w4[f0]; v = pn4[f0]; acc0 += w.x*v.x + w.y*v.y + w.z*v.z + w.w*v.w;
        w = w4[f1]; v = pn4[f1]; acc1 += w.x*v.x + w.y*v.y + w.z*v.z + w.w*v.w;
    }
    float val = acc0 + acc1;
    val += __shfl_xor_sync(0xFFFFFFFFu, val, 1);
    val += __shfl_xor_sync(0xFFFFFFFFu, val, 2);
    if (t == 0) sh_res[o] = val;
    __syncthreads();

    if (tid < 64) {
        if (tid < 32) {
            float v1 = sh_res[tid] + b1[tid];
            uint32_t hu, lu;
            bf16_split(v1, hu, lu);
            uint32_t hu1 = __shfl_down_sync(0xFFFFFFFFu, hu, 1);
            uint32_t lu1 = __shfl_down_sync(0xFFFFFFFFu, lu, 1);
            if ((tid & 1) == 0) {
                const int cch  = tid;
                const int it   = s >> 4;
                const int grow = s & 15;
                const int g    = grow & 7;
                const int top  = grow >> 3;
                const int ks   = cch >> 4;
                const int cl   = cch & 15;
                const int rhi  = cl >> 3;
                const int tt   = (cl & 7) >> 1;
                const int reg  = top + 2 * rhi;
                const int ln   = g * 4 + tt;
                const int i0 = ((((b * 2 + 0) * 2 + ks) * 12 + it) * 32 + ln) * 4 + reg;
                const int i1 = ((((b * 2 + 1) * 2 + ks) * 12 + it) * 32 + ln) * 4 + reg;
                g_p1f[i0] = hu | (hu1 << 16);
                g_p1f[i1] = lu | (lu1 << 16);
            }
        } else {
            float v2 = sh_res[tid] + b2[tid - 32];
            g_p2t[(b * C + (tid - 32)) * SEQ + s] = v2;
        }
    }
}

// ---------------------------------------------------------------------------
// Kernel 3 (R13 version — measured best: 18.3us).
// grid = 768 (bk x 3 j-thirds of 64 cols), 256 threads, launch_bounds(256,2).
// shW staged + LDS.128 W reads; qq hoisted above barrier; per-ks late A loads;
// per-warp smem-staged coalesced STG.128 epilogue.
// ---------------------------------------------------------------------------
#define STG_PITCH 40   // floats per staged row (conflict-free STS.64 / LDS.128)

__global__ __launch_bounds__(256, 2)
void k3_fused(const float* __restrict__ Wout,
              const float* __restrict__ bout,
              float* __restrict__ out) {
    const int blk    = blockIdx.x;
    const int bk     = blk / 3;
    const int jthird = blk - 3 * bk;
    const int b      = bk >> 7;
    const int k      = bk & (C_I - 1);
    const int tid    = threadIdx.x;
    const int wid    = tid >> 5, lane = tid & 31;
    const int wi     = wid >> 1;                 // 0..3 i-band (48 rows)
    const int wj     = wid & 1;                  // 0..1 j-band (32 cols)

    __shared__ float    shW[C * C];              // 4 KB
    __shared__ uint32_t sB[2 * 2 * 8 * 32 * 2];  // 8 KB fragments (64 cols)
    __shared__ float    sStage[8][16 * STG_PITCH + 8];  // 20.7 KB staging

    ((float4*)shW)[tid] = ((const float4*)(Wout + (size_t)k * C * C))[tid];

    // ---- M-build operand loads (independent of smem: issue before sync) ----
    const int jloc = tid & 63;
    const int rest = tid >> 6;
    const int ks   = rest & 1;
    const int ch   = rest >> 1;
    const int j    = jthird * 64 + jloc;
    const float* P2 = g_p2t + (size_t)b * C * SEQ;

    unsigned long long qq[16];
    #pragma unroll
    for (int d2 = 0; d2 < 16; ++d2) {
        float qa = P2[(2 * d2 + 0) * SEQ + j];
        float qb = P2[(2 * d2 + 1) * SEQ + j];
        PACK_F32X2(qq[d2], qa, qb);
    }
    __syncthreads();

    // ---- M build: thread = (jloc, ks, ch), 8 c's each ----
    {
        const int jt = jloc >> 3;
        const int g  = jloc & 7;
        float m[8];
        #pragma unroll
        for (int cc = 0; cc < 8; ++cc) {
            const int c = ks * 16 + ch * 8 + cc;
            const uint4* w4 = (const uint4*)(shW + c * C);
            unsigned long long acca = 0ull, accb = 0ull;
            #pragma unroll
            for (int d4 = 0; d4 < 4; ++d4) {
                uint4 wlo = w4[d4];
                uint4 whi = w4[d4 + 4];
                unsigned long long w0, w1, w2v, w3;
                asm("mov.b64 %0, {%1, %2};" : "=l"(w0) : "r"(wlo.x), "r"(wlo.y));
                asm("mov.b64 %0, {%1, %2};" : "=l"(w1) : "r"(wlo.z), "r"(wlo.w));
                asm("mov.b64 %0, {%1, %2};" : "=l"(w2v) : "r"(whi.x), "r"(whi.y));
                asm("mov.b64 %0, {%1, %2};" : "=l"(w3) : "r"(whi.z), "r"(whi.w));
                FMA_F32X2(acca, qq[2 * d4 + 0],     w0,  acca);
                FMA_F32X2(acca, qq[2 * d4 + 1],     w1,  acca);
                FMA_F32X2(accb, qq[8 + 2 * d4 + 0], w2v, accb);
                FMA_F32X2(accb, qq[8 + 2 * d4 + 1], w3,  accb);
            }
            float la, ha, lb2, hb2;
            UNPACK_F32X2(la, ha, acca);
            UNPACK_F32X2(lb2, hb2, accb);
            m[cc] = (la + ha) + (lb2 + hb2);
        }
        #pragma unroll
        for (int t = 0; t < 4; ++t) {
            uint32_t h0, l0, h1, l1;
            bf16_split(m[2 * t],     h0, l0);
            bf16_split(m[2 * t + 1], h1, l1);
            const int ln = g * 4 + t;
            sB[((0 * 2 + ks) * 8 + jt) * 64 + ln * 2 + ch] = h0 | (h1 << 16);
            sB[((1 * 2 + ks) * 8 + jt) * 64 + ln * 2 + ch] = l0 | (l1 << 16);
        }
    }
    __syncthreads();

    // ---- MMA ----
    float acc[3][4][4];
    #pragma unroll
    for (int i = 0; i < 3; ++i)
        #pragma unroll
        for (int jx = 0; jx < 4; ++jx)
            #pragma unroll
            for (int q = 0; q < 4; ++q) acc[i][jx][q] = 0.0f;

    const uint4* Af = (const uint4*)g_p1f;

    #pragma unroll
    for (int kss = 0; kss < 2; ++kss) {
        uint2 Bh[4];
        #pragma unroll
        for (int jtl = 0; jtl < 4; ++jtl) {
            const int jt = wj * 4 + jtl;
            Bh[jtl] = *(const uint2*)&sB[((0 * 2 + kss) * 8 + jt) * 64 + lane * 2];
        }
        uint4 Ah[3];
        #pragma unroll
        for (int itl = 0; itl < 3; ++itl)
            Ah[itl] = Af[(((b * 2 + 0) * 2 + kss) * 12 + (wi * 3 + itl)) * 32 + lane];
        #pragma unroll
        for (int itl = 0; itl < 3; ++itl)
            #pragma unroll
            for (int jtl = 0; jtl < 4; ++jtl)
                MMA_BF16(acc[itl][jtl], Ah[itl], Bh[jtl]);

        {
            uint4 Al[3];
            #pragma unroll
            for (int itl = 0; itl < 3; ++itl)
                Al[itl] = Af[(((b * 2 + 1) * 2 + kss) * 12 + (wi * 3 + itl)) * 32 + lane];
            #pragma unroll
            for (int itl = 0; itl < 3; ++itl)
                #pragma unroll
                for (int jtl = 0; jtl < 4; ++jtl)
                    MMA_BF16(acc[itl][jtl], Al[itl], Bh[jtl]);
        }
        {
            uint2 Bl[4];
            #pragma unroll
            for (int jtl = 0; jtl < 4; ++jtl) {
                const int jt = wj * 4 + jtl;
                Bl[jtl] = *(const uint2*)&sB[((1 * 2 + kss) * 8 + jt) * 64 + lane * 2];
            }
            #pragma unroll
            for (int itl = 0; itl < 3; ++itl)
                #pragma unroll
                for (int jtl = 0; jtl < 4; ++jtl)
                    MMA_BF16(acc[itl][jtl], Ah[itl], Bl[jtl]);
        }
    }

    // ---- epilogue: per-warp smem staging -> coalesced STG.128 ----
    const float bias = bout[k];
    const int g = lane >> 2, t = lane & 3;
    float* st = sStage[wid];
    const int rlo = lane >> 3;
    const int cs  = lane & 7;
    float* ob = out + (size_t)bk * SEQ * SEQ + jthird * 64 + wj * 32;

    #pragma unroll
    for (int itl = 0; itl < 3; ++itl) {
        #pragma unroll
        for (int jtl = 0; jtl < 4; ++jtl) {
            const int col = jtl * 8 + 2 * t;
            float2 v0, v1;
            v0.x = (acc[itl][jtl][0] + bias) * 0.5f;
            v0.y = (acc[itl][jtl][1] + bias) * 0.5f;
            v1.x = (acc[itl][jtl][2] + bias) * 0.5f;
            v1.y = (acc[itl][jtl][3] + bias) * 0.5f;
            *(float2*)&st[g * STG_PITCH + col]       = v0;
            *(float2*)&st[(g + 8) * STG_PITCH + col] = v1;
        }
        __syncwarp();
        #pragma unroll
        for (int rr = 0; rr < 4; ++rr) {
            const int rloc = rr * 4 + rlo;
            float4 v = *(const float4*)&st[rloc * STG_PITCH + cs * 4];
            const int grow = wi * 48 + itl * 16 + rloc;
            *(float4*)(ob + (size_t)grow * SEQ + cs * 4) = v;
        }
        __syncwarp();
    }
}

// ---------------------------------------------------------------------------
extern "C" void kernel_launch(void* const* d_in, const int* in_sizes, int n_in,
                              void* d_out, int out_size) {
    const float* p     = (const float*)d_in[0];
    const float* gamma = (const float*)d_in[1];
    const float* beta  = (const float*)d_in[2];
    const float* W1    = (const float*)d_in[3];
    const float* b1    = (const float*)d_in[4];
    const float* W2    = (const float*)d_in[5];
    const float* b2    = (const float*)d_in[6];
    const float* Wout  = (const float*)d_in[7];
    const float* bout  = (const float*)d_in[8];
    float* out = (float*)d_out;

    k1_ln_proj<<<SEQ * BATCH, 256>>>(p, gamma, beta, W1, b1, W2, b2);
    k3_fused<<<BATCH * C_I * 3, 256>>>(Wout, bout, out);
}